// round 16
// baseline (speedup 1.0000x reference)
#include <cuda_runtime.h>
#include <cuda_bf16.h>
#include <cstdint>

#define B_   64
#define T_   1024
#define F_   256
#define U_   512
#define G_   1536             // 3*U
#define P_   1024             // 2*U
#define GB_  (G_*B_)          // 98304
#define HB_  (U_*B_)          // 32768 floats per h ping-pong buffer
#define BT_  65536            // B*T
#define EPS_ 1e-3f

// ---------------------------------------------------------------------------
// Scratch: __device__ globals (allocation-free per harness rules)
// ---------------------------------------------------------------------------
__device__ float g_xwf[(size_t)T_ * G_ * B_];   // [T][G][B]  x@Wf + bi_f
__device__ float g_xwb[(size_t)T_ * G_ * B_];   // [T][G][B]  x@Wb + bi_b
__device__ float g_resid[(size_t)B_ * T_ * P_]; // [B*T][P]   x@Wp
__device__ float g_hf[(size_t)B_ * T_ * U_];    // [B][T][U]
__device__ float g_hb[(size_t)B_ * T_ * U_];    // [B][T][U]
__device__ float g_hbuf[2 * 2 * HB_];           // h ping-pong [dir][parity][kp][b]
__device__ unsigned g_cnt[2];                   // monotonic arrival counters

// bf16 hi/lo split buffers
__device__ unsigned short g_xhi[(size_t)BT_ * F_];
__device__ unsigned short g_xlo[(size_t)BT_ * F_];
__device__ unsigned short g_wfhi[F_ * G_], g_wflo[F_ * G_];
__device__ unsigned short g_wbhi[F_ * G_], g_wblo[F_ * G_];
__device__ unsigned short g_wphi[F_ * P_], g_wplo[F_ * P_];

// ---------------------------------------------------------------------------
// f32x2 packed FMA (Blackwell dual-fp32; only reachable via PTX)
// ---------------------------------------------------------------------------
__device__ __forceinline__ void fma2(float2& d, float2 a, float2 b) {
    unsigned long long& dd = reinterpret_cast<unsigned long long&>(d);
    unsigned long long& aa = reinterpret_cast<unsigned long long&>(a);
    unsigned long long& bb = reinterpret_cast<unsigned long long&>(b);
    asm("fma.rn.f32x2 %0, %1, %2, %0;" : "+l"(dd) : "l"(aa), "l"(bb));
}

// ---------------------------------------------------------------------------
__global__ void init_kernel() {
    int idx = blockIdx.x * blockDim.x + threadIdx.x;
    int stride = gridDim.x * blockDim.x;
    for (int i = idx; i < 2 * 2 * HB_; i += stride) g_hbuf[i] = 0.0f;
    if (idx < 2) g_cnt[idx] = 0u;
}

// ---------------------------------------------------------------------------
// bf16 hi/lo split converters
// ---------------------------------------------------------------------------
__device__ __forceinline__ void splitbf(float v, unsigned short& h, unsigned short& l) {
    __nv_bfloat16 hb = __float2bfloat16_rn(v);
    __nv_bfloat16 lb = __float2bfloat16_rn(v - __bfloat162float(hb));
    h = __bfloat16_as_ushort(hb);
    l = __bfloat16_as_ushort(lb);
}

__global__ void __launch_bounds__(256) convx_kernel(const float* __restrict__ x) {
    size_t i = (size_t)blockIdx.x * 256 + threadIdx.x;   // one float4 per thread
    float4 v = ((const float4*)x)[i];
    unsigned short h[4], l[4];
    splitbf(v.x, h[0], l[0]);
    splitbf(v.y, h[1], l[1]);
    splitbf(v.z, h[2], l[2]);
    splitbf(v.w, h[3], l[3]);
    uint2 hv, lv;
    hv.x = ((uint32_t)h[1] << 16) | h[0];
    hv.y = ((uint32_t)h[3] << 16) | h[2];
    lv.x = ((uint32_t)l[1] << 16) | l[0];
    lv.y = ((uint32_t)l[3] << 16) | l[2];
    ((uint2*)g_xhi)[i] = hv;
    ((uint2*)g_xlo)[i] = lv;
}

__global__ void __launch_bounds__(256) convw_kernel(
    const float* __restrict__ W, unsigned short* hi, unsigned short* lo, int n)
{
    int i = blockIdx.x * 256 + threadIdx.x;
    if (i < n) splitbf(W[i], hi[i], lo[i]);
}

// ---------------------------------------------------------------------------
// HMMA bf16-split GEMM: D[128,64] = x[128,256] @ W[256,64] via
// hi*hi + hi*lo + lo*hi, fp32 register accumulators.
// mma.sync.m16n8k16 (sm_80+ baseline feature; works on plain sm_103 target).
// Block 128x64, 256 thr = 8 warps (4M x 2N), warp tile 32x32 = 2x4 mma.
// K loop: 3 split products x 16 k-steps = 48 iters, register-prefetched.
// mode 0: xw fused (grid.y 0..47; y<24 -> f, else b; out [t][g][b] + bias)
// mode 1: resid    (grid.y 0..15; out [r][c])
// ---------------------------------------------------------------------------
__device__ __forceinline__ void mma16816(float* c, const uint32_t* a, const uint32_t* b) {
    asm volatile(
        "mma.sync.aligned.m16n8k16.row.col.f32.bf16.bf16.f32 "
        "{%0,%1,%2,%3}, {%4,%5,%6,%7}, {%8,%9}, {%0,%1,%2,%3};"
        : "+f"(c[0]), "+f"(c[1]), "+f"(c[2]), "+f"(c[3])
        : "r"(a[0]), "r"(a[1]), "r"(a[2]), "r"(a[3]), "r"(b[0]), "r"(b[1]));
}

__global__ void __launch_bounds__(256) mmagemm_kernel(
    const float* __restrict__ bf_, const float* __restrict__ bb_, int mode)
{
    __shared__ __align__(16) unsigned short As[128 * 16];  // [row][k] row-major
    __shared__ __align__(16) unsigned short Bs[64 * 16];   // [n][k] (transposed)

    int tid  = threadIdx.x;
    int warp = tid >> 5;
    int lane = tid & 31;
    int wm   = warp >> 1;        // 0..3  (M 32-tiles)
    int wn   = warp & 1;         // 0..1  (N 32-tiles)
    int g    = lane >> 2;        // 0..7
    int tig  = lane & 3;         // 0..3

    int row0 = blockIdx.x * 128;
    const unsigned short *Whi, *Wlo;
    const float* bias = nullptr;
    float* outp = nullptr;
    int Nw, col0;
    if (mode == 0) {
        int ysel = blockIdx.y >= 24;
        Whi  = ysel ? g_wbhi : g_wfhi;
        Wlo  = ysel ? g_wblo : g_wflo;
        bias = ysel ? bb_ : bf_;
        outp = ysel ? g_xwb : g_xwf;
        Nw   = G_;
        col0 = (blockIdx.y - (ysel ? 24 : 0)) * 64;
    } else {
        Whi  = g_wphi;
        Wlo  = g_wplo;
        Nw   = P_;
        col0 = blockIdx.y * 64;
    }

    // loader roles
    int arow  = tid >> 1;          // 0..127
    int acol8 = (tid & 1) * 8;     // 0 or 8
    int bk    = tid >> 4;          // 0..15
    int bn4   = (tid & 15) * 4;    // 0..60

    float c[2][4][4];
#pragma unroll
    for (int mt = 0; mt < 2; mt++)
#pragma unroll
        for (int nt = 0; nt < 4; nt++)
#pragma unroll
            for (int j = 0; j < 4; j++) c[mt][nt][j] = 0.f;

    // preload iter 0
    uint4 aREG = *(const uint4*)(g_xhi + (size_t)(row0 + arow) * F_ + acol8);
    uint2 bREG = *(const uint2*)(Whi + (size_t)bk * Nw + col0 + bn4);

#pragma unroll 1
    for (int it = 0; it < 48; it++) {
        // stage current tile
        *(uint4*)&As[arow * 16 + acol8] = aREG;
        Bs[(bn4 + 0) * 16 + bk] = (unsigned short)(bREG.x & 0xFFFF);
        Bs[(bn4 + 1) * 16 + bk] = (unsigned short)(bREG.x >> 16);
        Bs[(bn4 + 2) * 16 + bk] = (unsigned short)(bREG.y & 0xFFFF);
        Bs[(bn4 + 3) * 16 + bk] = (unsigned short)(bREG.y >> 16);
        __syncthreads();

        // prefetch next tile
        if (it < 47) {
            int nit = it + 1;
            int seg = nit >> 4;
            int kk  = (nit & 15) * 16;
            const unsigned short* Aseg = (seg == 2) ? g_xlo : g_xhi;
            const unsigned short* Bseg = (seg == 1) ? Wlo : Whi;
            aREG = *(const uint4*)(Aseg + (size_t)(row0 + arow) * F_ + kk + acol8);
            bREG = *(const uint2*)(Bseg + (size_t)(kk + bk) * Nw + col0 + bn4);
        }

        // compute: 2 A-frag sets x 4 B-frag sets
        uint32_t afr[2][4];
#pragma unroll
        for (int mt = 0; mt < 2; mt++) {
            int mb = wm * 32 + mt * 16;
            afr[mt][0] = *(const uint32_t*)&As[(mb + g)     * 16 + 2 * tig];
            afr[mt][1] = *(const uint32_t*)&As[(mb + g + 8) * 16 + 2 * tig];
            afr[mt][2] = *(const uint32_t*)&As[(mb + g)     * 16 + 2 * tig + 8];
            afr[mt][3] = *(const uint32_t*)&As[(mb + g + 8) * 16 + 2 * tig + 8];
        }
#pragma unroll
        for (int nt = 0; nt < 4; nt++) {
            int nb = wn * 32 + nt * 8 + g;
            uint32_t bfr[2];
            bfr[0] = *(const uint32_t*)&Bs[nb * 16 + 2 * tig];
            bfr[1] = *(const uint32_t*)&Bs[nb * 16 + 2 * tig + 8];
#pragma unroll
            for (int mt = 0; mt < 2; mt++)
                mma16816(c[mt][nt], afr[mt], bfr);
        }
        __syncthreads();
    }

    // ---- epilogue ----
    if (mode == 0) {
#pragma unroll
        for (int mt = 0; mt < 2; mt++) {
#pragma unroll
            for (int half = 0; half < 2; half++) {
                int r = row0 + wm * 32 + mt * 16 + g + half * 8;
                int b = r >> 10;
                int t = r & 1023;
                float* orow = outp + (size_t)t * GB_;
#pragma unroll
                for (int nt = 0; nt < 4; nt++) {
                    int gc = col0 + wn * 32 + nt * 8 + 2 * tig;
                    orow[(size_t)gc * B_ + b]       = c[mt][nt][half * 2 + 0] + __ldg(&bias[gc]);
                    orow[(size_t)(gc + 1) * B_ + b] = c[mt][nt][half * 2 + 1] + __ldg(&bias[gc + 1]);
                }
            }
        }
    } else {
#pragma unroll
        for (int mt = 0; mt < 2; mt++) {
#pragma unroll
            for (int half = 0; half < 2; half++) {
                int r = row0 + wm * 32 + mt * 16 + g + half * 8;
                float* orow = g_resid + (size_t)r * P_;
#pragma unroll
                for (int nt = 0; nt < 4; nt++) {
                    int gc = col0 + wn * 32 + nt * 8 + 2 * tig;
                    *(float2*)(orow + gc) =
                        make_float2(c[mt][nt][half * 2 + 0], c[mt][nt][half * 2 + 1]);
                }
            }
        }
    }
}

// ---------------------------------------------------------------------------
// GRU recurrence v14 (unchanged from best-passing R14).
// ---------------------------------------------------------------------------
__global__ void __launch_bounds__(512) gru_kernel(
    const float* __restrict__ Ufm, const float* __restrict__ Ubm,
    const float* __restrict__ bfv, const float* __restrict__ bbv)
{
    extern __shared__ float smem_[];
    float* Us   = smem_;                         // [24][512]
    float* part = smem_ + 24 * 512;              // [16][12][64]
#define PARTF(w, c, b) part[(((w) * 12 + (c)) << 6) + (b)]

    int tid = threadIdx.x;
    int dir = blockIdx.x >> 6;
    int jb  = blockIdx.x & 63;

    const float* Um    = dir ? Ubm : Ufm;
    const float* brv   = (dir ? bbv : bfv) + G_;
    const float* xw    = dir ? g_xwb : g_xwf;
    float*       hout  = dir ? g_hb  : g_hf;
    float*       hbase = g_hbuf + (size_t)dir * 2 * HB_;

    for (int idx = tid; idx < 24 * 512; idx += 512) {
        int c = idx >> 9;
        int k = idx & 511;
        int g  = c >> 3;
        int uu = c & 7;
        Us[c * 512 + k] = Um[(size_t)k * G_ + g * U_ + jb * 8 + uu];
    }

    int w    = tid >> 5;
    int lane = tid & 31;
    int ch   = w & 1;
    int kw   = w >> 1;
    int cbase = ch * 12;

    int uf   = tid >> 6;
    int bfin = tid & 63;
    int fug  = jb * 8 + uf;
    float brz = brv[fug];
    float brr = brv[U_ + fug];
    float brh = brv[2 * U_ + fug];
    int chr = (uf >= 4) ? 1 : 0;
    int clr = (uf >= 4) ? (uf - 4) : (8 + uf);

    const float4* U4 = (const float4*)Us;

    __syncthreads();

    for (int s = 0; s < T_; s++) {
        int tt = dir ? (T_ - 1 - s) : s;
        int par = s & 1;
        const float* HcF = hbase + (size_t)par * HB_;
        float*       HnF = hbase + (size_t)(par ^ 1) * HB_;
        const float4* Hq = (const float4*)HcF + (size_t)(kw * 32) * 32 + lane;

        const float* XW = xw + (size_t)tt * GB_;
        float xz = XW[(0 * U_ + fug) * B_ + bfin];
        float xr = XW[(1 * U_ + fug) * B_ + bfin];
        float xh = XW[(2 * U_ + fug) * B_ + bfin];
        float2 hv = ((const float2*)HcF)[(size_t)(fug >> 1) * 64 + bfin];
        float hold = (uf & 1) ? hv.y : hv.x;

        if (s > 0) {
            if (tid == 0) {
                volatile unsigned* vc = &g_cnt[dir];
                unsigned target = (unsigned)(64 * s);
                while (*vc < target) { }
                __threadfence();
            }
            __syncthreads();
        }

        float2 acc0[12], acc1[12];
#pragma unroll
        for (int c = 0; c < 12; c++) { acc0[c] = make_float2(0.f, 0.f); acc1[c] = make_float2(0.f, 0.f); }

        float4 bufA[4], bufB[4];
#pragma unroll
        for (int j = 0; j < 4; j++) bufA[j] = Hq[(size_t)j * 32];

#pragma unroll
        for (int seg = 0; seg < 8; seg++) {
            float4* cur = (seg & 1) ? bufB : bufA;
            float4* nxt = (seg & 1) ? bufA : bufB;
            if (seg < 7) {
#pragma unroll
                for (int j = 0; j < 4; j++)
                    nxt[j] = Hq[(size_t)((seg + 1) * 4 + j) * 32];
            }
#pragma unroll
            for (int half = 0; half < 2; half++) {
                float4 h0 = cur[2 * half];
                float4 h1 = cur[2 * half + 1];
#pragma unroll
                for (int c = 0; c < 12; c++) {
                    float4 u = U4[(cbase + c) * 128 + kw * 16 + 2 * seg + half];
                    fma2(acc0[c], make_float2(u.x, u.y), make_float2(h0.x, h0.y));
                    fma2(acc1[c], make_float2(u.x, u.y), make_float2(h0.z, h0.w));
                    fma2(acc0[c], make_float2(u.z, u.w), make_float2(h1.x, h1.y));
                    fma2(acc1[c], make_float2(u.z, u.w), make_float2(h1.z, h1.w));
                }
            }
        }

        float2* P2 = (float2*)part;
#pragma unroll
        for (int c = 0; c < 12; c++)
            P2[((w * 12 + c) << 5) + lane] =
                make_float2(acc0[c].x + acc0[c].y, acc1[c].x + acc1[c].y);
        __syncthreads();

        {
            float sz = 0.f, sr = 0.f, sh = 0.f;
#pragma unroll
            for (int k8 = 0; k8 < 8; k8++) {
                sz += PARTF(2 * k8 + 0,   uf,     bfin);
                sr += PARTF(2 * k8 + chr, clr,    bfin);
                sh += PARTF(2 * k8 + 1,   4 + uf, bfin);
            }
            float z  = 1.0f / (1.0f + expf(-(xz + sz + brz)));
            float r  = 1.0f / (1.0f + expf(-(xr + sr + brr)));
            float hh = tanhf(xh + r * (sh + brh));
            float hn = z * hold + (1.0f - z) * hh;

            HnF[(((size_t)(fug >> 1) * 64 + bfin) << 1) + (uf & 1)] = hn;
            __syncthreads();

            if (tid == 0) {
                __threadfence();
                atomicAdd(&g_cnt[dir], 1u);
            }
            hout[((size_t)bfin * T_ + tt) * U_ + fug] = hn;
        }
    }
#undef PARTF
}

// ---------------------------------------------------------------------------
// Epilogue: y = concat(hf,hb) + resid; LayerNorm over last dim (1024)
// ---------------------------------------------------------------------------
__global__ void __launch_bounds__(256) ln_kernel(
    const float* __restrict__ gamma, const float* __restrict__ beta,
    float* __restrict__ out)
{
    __shared__ float red[2][8];
    int row = blockIdx.x;
    int tid = threadIdx.x;
    int c   = tid * 4;

    const float* hsrc = (tid < 128)
        ? (g_hf + (size_t)row * U_ + c)
        : (g_hb + (size_t)row * U_ + (c - U_));
    float4 h4 = *(const float4*)hsrc;
    float4 r4 = *(const float4*)(g_resid + (size_t)row * P_ + c);

    float y0 = h4.x + r4.x, y1 = h4.y + r4.y, y2 = h4.z + r4.z, y3 = h4.w + r4.w;
    float s  = y0 + y1 + y2 + y3;
    float s2 = y0 * y0 + y1 * y1 + y2 * y2 + y3 * y3;

#pragma unroll
    for (int off = 16; off > 0; off >>= 1) {
        s  += __shfl_xor_sync(0xFFFFFFFFu, s,  off);
        s2 += __shfl_xor_sync(0xFFFFFFFFu, s2, off);
    }
    int wid = tid >> 5, lane = tid & 31;
    if (lane == 0) { red[0][wid] = s; red[1][wid] = s2; }
    __syncthreads();
    s = 0.f; s2 = 0.f;
#pragma unroll
    for (int i = 0; i < 8; i++) { s += red[0][i]; s2 += red[1][i]; }

    float mu  = s * (1.0f / 1024.0f);
    float var = s2 * (1.0f / 1024.0f) - mu * mu;
    float inv = rsqrtf(var + EPS_);

    float4 g4 = *(const float4*)(gamma + c);
    float4 b4 = *(const float4*)(beta + c);
    float4 o;
    o.x = g4.x * (y0 - mu) * inv + b4.x;
    o.y = g4.y * (y1 - mu) * inv + b4.y;
    o.z = g4.z * (y2 - mu) * inv + b4.z;
    o.w = g4.w * (y3 - mu) * inv + b4.w;
    *(float4*)(out + (size_t)row * P_ + c) = o;
}

// ---------------------------------------------------------------------------
extern "C" void kernel_launch(void* const* d_in, const int* in_sizes, int n_in,
                              void* d_out, int out_size) {
    const float* x     = (const float*)d_in[0];
    const float* Wf    = (const float*)d_in[1];
    const float* Uf    = (const float*)d_in[2];
    const float* bf    = (const float*)d_in[3];
    const float* Wb    = (const float*)d_in[4];
    const float* Ub    = (const float*)d_in[5];
    const float* bb    = (const float*)d_in[6];
    const float* Wp    = (const float*)d_in[7];
    const float* gamma = (const float*)d_in[8];
    const float* beta  = (const float*)d_in[9];
    float* out = (float*)d_out;

    unsigned short *wfhi, *wflo, *wbhi, *wblo, *wphi, *wplo;
    cudaGetSymbolAddress((void**)&wfhi, g_wfhi);
    cudaGetSymbolAddress((void**)&wflo, g_wflo);
    cudaGetSymbolAddress((void**)&wbhi, g_wbhi);
    cudaGetSymbolAddress((void**)&wblo, g_wblo);
    cudaGetSymbolAddress((void**)&wphi, g_wphi);
    cudaGetSymbolAddress((void**)&wplo, g_wplo);

    const int gru_smem = 24 * 512 * 4 + 16 * 12 * 64 * 4;  // 98304 B
    cudaFuncSetAttribute(gru_kernel, cudaFuncAttributeMaxDynamicSharedMemorySize, gru_smem);

    init_kernel<<<64, 256>>>();
    convx_kernel<<<BT_ * F_ / 4 / 256, 256>>>(x);
    convw_kernel<<<(F_ * G_ + 255) / 256, 256>>>(Wf, wfhi, wflo, F_ * G_);
    convw_kernel<<<(F_ * G_ + 255) / 256, 256>>>(Wb, wbhi, wblo, F_ * G_);
    convw_kernel<<<(F_ * P_ + 255) / 256, 256>>>(Wp, wphi, wplo, F_ * P_);

    mmagemm_kernel<<<dim3(BT_ / 128, 48), 256>>>(bf, bb, 0);
    mmagemm_kernel<<<dim3(BT_ / 128, 16), 256>>>(nullptr, nullptr, 1);

    gru_kernel<<<128, 512, gru_smem>>>(Uf, Ub, bf, bb);
    ln_kernel<<<B_ * T_, 256>>>(gamma, beta, out);
}

// round 17
// speedup vs baseline: 1.1270x; 1.1270x over previous
#include <cuda_runtime.h>
#include <cuda_bf16.h>
#include <cstdint>

#define B_   64
#define T_   1024
#define F_   256
#define U_   512
#define G_   1536             // 3*U
#define P_   1024             // 2*U
#define GB_  (G_*B_)          // 98304
#define HB_  (U_*B_)          // 32768 floats per h ping-pong buffer
#define BT_  65536            // B*T
#define EPS_ 1e-3f

// ---------------------------------------------------------------------------
// Scratch: __device__ globals (allocation-free per harness rules)
// ---------------------------------------------------------------------------
__device__ float g_xwf[(size_t)T_ * G_ * B_];   // [T][G][B]  x@Wf + bi_f
__device__ float g_xwb[(size_t)T_ * G_ * B_];   // [T][G][B]  x@Wb + bi_b
__device__ float g_resid[(size_t)B_ * T_ * P_]; // [B*T][P]   x@Wp
__device__ float g_hf[(size_t)B_ * T_ * U_];    // [B][T][U]
__device__ float g_hb[(size_t)B_ * T_ * U_];    // [B][T][U]
__device__ float g_hbuf[2 * 2 * HB_];           // h ping-pong [dir][parity][kp][b]
__device__ unsigned g_cnt[2];                   // monotonic arrival counters

// bf16 hi/lo split buffers
__device__ unsigned short g_xhi[(size_t)BT_ * F_];
__device__ unsigned short g_xlo[(size_t)BT_ * F_];
__device__ unsigned short g_wfhi[F_ * G_], g_wflo[F_ * G_];
__device__ unsigned short g_wbhi[F_ * G_], g_wblo[F_ * G_];
__device__ unsigned short g_wphi[F_ * P_], g_wplo[F_ * P_];

// ---------------------------------------------------------------------------
// f32x2 packed FMA (Blackwell dual-fp32; only reachable via PTX)
// ---------------------------------------------------------------------------
__device__ __forceinline__ void fma2(float2& d, float2 a, float2 b) {
    unsigned long long& dd = reinterpret_cast<unsigned long long&>(d);
    unsigned long long& aa = reinterpret_cast<unsigned long long&>(a);
    unsigned long long& bb = reinterpret_cast<unsigned long long&>(b);
    asm("fma.rn.f32x2 %0, %1, %2, %0;" : "+l"(dd) : "l"(aa), "l"(bb));
}

// ---------------------------------------------------------------------------
__global__ void init_kernel() {
    int idx = blockIdx.x * blockDim.x + threadIdx.x;
    int stride = gridDim.x * blockDim.x;
    for (int i = idx; i < 2 * 2 * HB_; i += stride) g_hbuf[i] = 0.0f;
    if (idx < 2) g_cnt[idx] = 0u;
}

// ---------------------------------------------------------------------------
// bf16 hi/lo split converters
// ---------------------------------------------------------------------------
__device__ __forceinline__ void splitbf(float v, unsigned short& h, unsigned short& l) {
    __nv_bfloat16 hb = __float2bfloat16_rn(v);
    __nv_bfloat16 lb = __float2bfloat16_rn(v - __bfloat162float(hb));
    h = __bfloat16_as_ushort(hb);
    l = __bfloat16_as_ushort(lb);
}

__global__ void __launch_bounds__(256) convx_kernel(const float* __restrict__ x) {
    size_t i = (size_t)blockIdx.x * 256 + threadIdx.x;   // one float4 per thread
    float4 v = ((const float4*)x)[i];
    unsigned short h[4], l[4];
    splitbf(v.x, h[0], l[0]);
    splitbf(v.y, h[1], l[1]);
    splitbf(v.z, h[2], l[2]);
    splitbf(v.w, h[3], l[3]);
    uint2 hv, lv;
    hv.x = ((uint32_t)h[1] << 16) | h[0];
    hv.y = ((uint32_t)h[3] << 16) | h[2];
    lv.x = ((uint32_t)l[1] << 16) | l[0];
    lv.y = ((uint32_t)l[3] << 16) | l[2];
    ((uint2*)g_xhi)[i] = hv;
    ((uint2*)g_xlo)[i] = lv;
}

__global__ void __launch_bounds__(256) convw_kernel(
    const float* __restrict__ W, unsigned short* hi, unsigned short* lo, int n)
{
    int i = blockIdx.x * 256 + threadIdx.x;
    if (i < n) splitbf(W[i], hi[i], lo[i]);
}

// ---------------------------------------------------------------------------
// HMMA bf16-split GEMM v2: full-K smem residency, ONE barrier per block.
// D[128,64] = x[128,256] @ W[256,64] via hi*hi + hi*lo + lo*hi (fp32 acc).
// smem (dynamic, padded rows of 264 bf16 for conflict-free frag LDS):
//   Ah[128][264], Al[128][264], Bh[64][264], Bl[64][264]  = 202752 B
// 256 thr = 8 warps (4M x 2N); warp tile 32x32 = 2x4 m16n8k16 per k-step;
// 48 k-steps (3 products x 16) back-to-back, no syncs.
// mode 0: xw fused (grid.y 0..47; y<24 -> f, else b; out [t][g][b] + bias)
// mode 1: resid    (grid.y 0..15; out [r][c])
// ---------------------------------------------------------------------------
#define APAD 264
#define SM_AH 0
#define SM_AL 33792
#define SM_BH 67584
#define SM_BL 84480
#define SM_TOT_ELEM 101376
#define MM_SMEM (SM_TOT_ELEM * 2)

__device__ __forceinline__ void mma16816(float* c, const uint32_t* a, const uint32_t* b) {
    asm volatile(
        "mma.sync.aligned.m16n8k16.row.col.f32.bf16.bf16.f32 "
        "{%0,%1,%2,%3}, {%4,%5,%6,%7}, {%8,%9}, {%0,%1,%2,%3};"
        : "+f"(c[0]), "+f"(c[1]), "+f"(c[2]), "+f"(c[3])
        : "r"(a[0]), "r"(a[1]), "r"(a[2]), "r"(a[3]), "r"(b[0]), "r"(b[1]));
}

__global__ void __launch_bounds__(256) mmagemm_kernel(
    const float* __restrict__ bf_, const float* __restrict__ bb_, int mode)
{
    extern __shared__ unsigned short sm[];
    unsigned short* Ah = sm + SM_AH;
    unsigned short* Al = sm + SM_AL;
    unsigned short* Bh = sm + SM_BH;
    unsigned short* Bl = sm + SM_BL;

    int tid  = threadIdx.x;
    int warp = tid >> 5;
    int lane = tid & 31;
    int wm   = warp >> 1;        // 0..3  (M 32-tiles)
    int wn   = warp & 1;         // 0..1  (N 32-tiles)
    int g    = lane >> 2;        // 0..7
    int tig  = lane & 3;         // 0..3

    int row0 = blockIdx.x * 128;
    const unsigned short *Whi, *Wlo;
    const float* bias = nullptr;
    float* outp = nullptr;
    int Nw, col0;
    if (mode == 0) {
        int ysel = blockIdx.y >= 24;
        Whi  = ysel ? g_wbhi : g_wfhi;
        Wlo  = ysel ? g_wblo : g_wflo;
        bias = ysel ? bb_ : bf_;
        outp = ysel ? g_xwb : g_xwf;
        Nw   = G_;
        col0 = (blockIdx.y - (ysel ? 24 : 0)) * 64;
    } else {
        Whi  = g_wphi;
        Wlo  = g_wplo;
        Nw   = P_;
        col0 = blockIdx.y * 64;
    }

    // ---- stage A (full K): thread -> (row = tid>>1, half = tid&1) ----
    {
        int arow  = tid >> 1;
        int ahalf = (tid & 1) * 128;
        const uint4* gah = (const uint4*)(g_xhi + (size_t)(row0 + arow) * F_ + ahalf);
        const uint4* gal = (const uint4*)(g_xlo + (size_t)(row0 + arow) * F_ + ahalf);
        uint4* sah = (uint4*)(Ah + arow * APAD + ahalf);
        uint4* sal = (uint4*)(Al + arow * APAD + ahalf);
#pragma unroll
        for (int j = 0; j < 16; j++) sah[j] = gah[j];
#pragma unroll
        for (int j = 0; j < 16; j++) sal[j] = gal[j];
    }
    // ---- stage B (full K, transposed to [n][k]) ----
    {
        int nn = tid & 63;
        int kq = tid >> 6;      // 0..3 -> k block of 64
#pragma unroll 8
        for (int kk = 0; kk < 64; kk++) {
            int k = kq * 64 + kk;
            Bh[nn * APAD + k] = Whi[(size_t)k * Nw + col0 + nn];
            Bl[nn * APAD + k] = Wlo[(size_t)k * Nw + col0 + nn];
        }
    }
    __syncthreads();   // the ONLY barrier

    float c[2][4][4];
#pragma unroll
    for (int mt = 0; mt < 2; mt++)
#pragma unroll
        for (int nt = 0; nt < 4; nt++)
#pragma unroll
            for (int j = 0; j < 4; j++) c[mt][nt][j] = 0.f;

#pragma unroll
    for (int seg = 0; seg < 3; seg++) {
        const unsigned short* A = (seg == 2) ? Al : Ah;
        const unsigned short* Bt = (seg == 1) ? Bl : Bh;
#pragma unroll
        for (int ks = 0; ks < 16; ks++) {
            int kk = ks * 16;
            uint32_t afr[2][4];
#pragma unroll
            for (int mt = 0; mt < 2; mt++) {
                int mb = wm * 32 + mt * 16;
                afr[mt][0] = *(const uint32_t*)&A[(mb + g)     * APAD + kk + 2 * tig];
                afr[mt][1] = *(const uint32_t*)&A[(mb + g + 8) * APAD + kk + 2 * tig];
                afr[mt][2] = *(const uint32_t*)&A[(mb + g)     * APAD + kk + 2 * tig + 8];
                afr[mt][3] = *(const uint32_t*)&A[(mb + g + 8) * APAD + kk + 2 * tig + 8];
            }
#pragma unroll
            for (int nt = 0; nt < 4; nt++) {
                int nb = wn * 32 + nt * 8 + g;
                uint32_t bfr[2];
                bfr[0] = *(const uint32_t*)&Bt[nb * APAD + kk + 2 * tig];
                bfr[1] = *(const uint32_t*)&Bt[nb * APAD + kk + 2 * tig + 8];
#pragma unroll
                for (int mt = 0; mt < 2; mt++)
                    mma16816(c[mt][nt], afr[mt], bfr);
            }
        }
    }

    // ---- epilogue (identical mapping to verified R16) ----
    if (mode == 0) {
#pragma unroll
        for (int mt = 0; mt < 2; mt++) {
#pragma unroll
            for (int half = 0; half < 2; half++) {
                int r = row0 + wm * 32 + mt * 16 + g + half * 8;
                int b = r >> 10;
                int t = r & 1023;
                float* orow = outp + (size_t)t * GB_;
#pragma unroll
                for (int nt = 0; nt < 4; nt++) {
                    int gc = col0 + wn * 32 + nt * 8 + 2 * tig;
                    orow[(size_t)gc * B_ + b]       = c[mt][nt][half * 2 + 0] + __ldg(&bias[gc]);
                    orow[(size_t)(gc + 1) * B_ + b] = c[mt][nt][half * 2 + 1] + __ldg(&bias[gc + 1]);
                }
            }
        }
    } else {
#pragma unroll
        for (int mt = 0; mt < 2; mt++) {
#pragma unroll
            for (int half = 0; half < 2; half++) {
                int r = row0 + wm * 32 + mt * 16 + g + half * 8;
                float* orow = g_resid + (size_t)r * P_;
#pragma unroll
                for (int nt = 0; nt < 4; nt++) {
                    int gc = col0 + wn * 32 + nt * 8 + 2 * tig;
                    *(float2*)(orow + gc) =
                        make_float2(c[mt][nt][half * 2 + 0], c[mt][nt][half * 2 + 1]);
                }
            }
        }
    }
}

// ---------------------------------------------------------------------------
// GRU recurrence v14 (unchanged from best-passing R14).
// ---------------------------------------------------------------------------
__global__ void __launch_bounds__(512) gru_kernel(
    const float* __restrict__ Ufm, const float* __restrict__ Ubm,
    const float* __restrict__ bfv, const float* __restrict__ bbv)
{
    extern __shared__ float smem_[];
    float* Us   = smem_;                         // [24][512]
    float* part = smem_ + 24 * 512;              // [16][12][64]
#define PARTF(w, c, b) part[(((w) * 12 + (c)) << 6) + (b)]

    int tid = threadIdx.x;
    int dir = blockIdx.x >> 6;
    int jb  = blockIdx.x & 63;

    const float* Um    = dir ? Ubm : Ufm;
    const float* brv   = (dir ? bbv : bfv) + G_;
    const float* xw    = dir ? g_xwb : g_xwf;
    float*       hout  = dir ? g_hb  : g_hf;
    float*       hbase = g_hbuf + (size_t)dir * 2 * HB_;

    for (int idx = tid; idx < 24 * 512; idx += 512) {
        int c = idx >> 9;
        int k = idx & 511;
        int g  = c >> 3;
        int uu = c & 7;
        Us[c * 512 + k] = Um[(size_t)k * G_ + g * U_ + jb * 8 + uu];
    }

    int w    = tid >> 5;
    int lane = tid & 31;
    int ch   = w & 1;
    int kw   = w >> 1;
    int cbase = ch * 12;

    int uf   = tid >> 6;
    int bfin = tid & 63;
    int fug  = jb * 8 + uf;
    float brz = brv[fug];
    float brr = brv[U_ + fug];
    float brh = brv[2 * U_ + fug];
    int chr = (uf >= 4) ? 1 : 0;
    int clr = (uf >= 4) ? (uf - 4) : (8 + uf);

    const float4* U4 = (const float4*)Us;

    __syncthreads();

    for (int s = 0; s < T_; s++) {
        int tt = dir ? (T_ - 1 - s) : s;
        int par = s & 1;
        const float* HcF = hbase + (size_t)par * HB_;
        float*       HnF = hbase + (size_t)(par ^ 1) * HB_;
        const float4* Hq = (const float4*)HcF + (size_t)(kw * 32) * 32 + lane;

        const float* XW = xw + (size_t)tt * GB_;
        float xz = XW[(0 * U_ + fug) * B_ + bfin];
        float xr = XW[(1 * U_ + fug) * B_ + bfin];
        float xh = XW[(2 * U_ + fug) * B_ + bfin];
        float2 hv = ((const float2*)HcF)[(size_t)(fug >> 1) * 64 + bfin];
        float hold = (uf & 1) ? hv.y : hv.x;

        if (s > 0) {
            if (tid == 0) {
                volatile unsigned* vc = &g_cnt[dir];
                unsigned target = (unsigned)(64 * s);
                while (*vc < target) { }
                __threadfence();
            }
            __syncthreads();
        }

        float2 acc0[12], acc1[12];
#pragma unroll
        for (int c = 0; c < 12; c++) { acc0[c] = make_float2(0.f, 0.f); acc1[c] = make_float2(0.f, 0.f); }

        float4 bufA[4], bufB[4];
#pragma unroll
        for (int j = 0; j < 4; j++) bufA[j] = Hq[(size_t)j * 32];

#pragma unroll
        for (int seg = 0; seg < 8; seg++) {
            float4* cur = (seg & 1) ? bufB : bufA;
            float4* nxt = (seg & 1) ? bufA : bufB;
            if (seg < 7) {
#pragma unroll
                for (int j = 0; j < 4; j++)
                    nxt[j] = Hq[(size_t)((seg + 1) * 4 + j) * 32];
            }
#pragma unroll
            for (int half = 0; half < 2; half++) {
                float4 h0 = cur[2 * half];
                float4 h1 = cur[2 * half + 1];
#pragma unroll
                for (int c = 0; c < 12; c++) {
                    float4 u = U4[(cbase + c) * 128 + kw * 16 + 2 * seg + half];
                    fma2(acc0[c], make_float2(u.x, u.y), make_float2(h0.x, h0.y));
                    fma2(acc1[c], make_float2(u.x, u.y), make_float2(h0.z, h0.w));
                    fma2(acc0[c], make_float2(u.z, u.w), make_float2(h1.x, h1.y));
                    fma2(acc1[c], make_float2(u.z, u.w), make_float2(h1.z, h1.w));
                }
            }
        }

        float2* P2 = (float2*)part;
#pragma unroll
        for (int c = 0; c < 12; c++)
            P2[((w * 12 + c) << 5) + lane] =
                make_float2(acc0[c].x + acc0[c].y, acc1[c].x + acc1[c].y);
        __syncthreads();

        {
            float sz = 0.f, sr = 0.f, sh = 0.f;
#pragma unroll
            for (int k8 = 0; k8 < 8; k8++) {
                sz += PARTF(2 * k8 + 0,   uf,     bfin);
                sr += PARTF(2 * k8 + chr, clr,    bfin);
                sh += PARTF(2 * k8 + 1,   4 + uf, bfin);
            }
            float z  = 1.0f / (1.0f + expf(-(xz + sz + brz)));
            float r  = 1.0f / (1.0f + expf(-(xr + sr + brr)));
            float hh = tanhf(xh + r * (sh + brh));
            float hn = z * hold + (1.0f - z) * hh;

            HnF[(((size_t)(fug >> 1) * 64 + bfin) << 1) + (uf & 1)] = hn;
            __syncthreads();

            if (tid == 0) {
                __threadfence();
                atomicAdd(&g_cnt[dir], 1u);
            }
            hout[((size_t)bfin * T_ + tt) * U_ + fug] = hn;
        }
    }
#undef PARTF
}

// ---------------------------------------------------------------------------
// Epilogue: y = concat(hf,hb) + resid; LayerNorm over last dim (1024)
// ---------------------------------------------------------------------------
__global__ void __launch_bounds__(256) ln_kernel(
    const float* __restrict__ gamma, const float* __restrict__ beta,
    float* __restrict__ out)
{
    __shared__ float red[2][8];
    int row = blockIdx.x;
    int tid = threadIdx.x;
    int c   = tid * 4;

    const float* hsrc = (tid < 128)
        ? (g_hf + (size_t)row * U_ + c)
        : (g_hb + (size_t)row * U_ + (c - U_));
    float4 h4 = *(const float4*)hsrc;
    float4 r4 = *(const float4*)(g_resid + (size_t)row * P_ + c);

    float y0 = h4.x + r4.x, y1 = h4.y + r4.y, y2 = h4.z + r4.z, y3 = h4.w + r4.w;
    float s  = y0 + y1 + y2 + y3;
    float s2 = y0 * y0 + y1 * y1 + y2 * y2 + y3 * y3;

#pragma unroll
    for (int off = 16; off > 0; off >>= 1) {
        s  += __shfl_xor_sync(0xFFFFFFFFu, s,  off);
        s2 += __shfl_xor_sync(0xFFFFFFFFu, s2, off);
    }
    int wid = tid >> 5, lane = tid & 31;
    if (lane == 0) { red[0][wid] = s; red[1][wid] = s2; }
    __syncthreads();
    s = 0.f; s2 = 0.f;
#pragma unroll
    for (int i = 0; i < 8; i++) { s += red[0][i]; s2 += red[1][i]; }

    float mu  = s * (1.0f / 1024.0f);
    float var = s2 * (1.0f / 1024.0f) - mu * mu;
    float inv = rsqrtf(var + EPS_);

    float4 g4 = *(const float4*)(gamma + c);
    float4 b4 = *(const float4*)(beta + c);
    float4 o;
    o.x = g4.x * (y0 - mu) * inv + b4.x;
    o.y = g4.y * (y1 - mu) * inv + b4.y;
    o.z = g4.z * (y2 - mu) * inv + b4.z;
    o.w = g4.w * (y3 - mu) * inv + b4.w;
    *(float4*)(out + (size_t)row * P_ + c) = o;
}

// ---------------------------------------------------------------------------
extern "C" void kernel_launch(void* const* d_in, const int* in_sizes, int n_in,
                              void* d_out, int out_size) {
    const float* x     = (const float*)d_in[0];
    const float* Wf    = (const float*)d_in[1];
    const float* Uf    = (const float*)d_in[2];
    const float* bf    = (const float*)d_in[3];
    const float* Wb    = (const float*)d_in[4];
    const float* Ub    = (const float*)d_in[5];
    const float* bb    = (const float*)d_in[6];
    const float* Wp    = (const float*)d_in[7];
    const float* gamma = (const float*)d_in[8];
    const float* beta  = (const float*)d_in[9];
    float* out = (float*)d_out;

    unsigned short *wfhi, *wflo, *wbhi, *wblo, *wphi, *wplo;
    cudaGetSymbolAddress((void**)&wfhi, g_wfhi);
    cudaGetSymbolAddress((void**)&wflo, g_wflo);
    cudaGetSymbolAddress((void**)&wbhi, g_wbhi);
    cudaGetSymbolAddress((void**)&wblo, g_wblo);
    cudaGetSymbolAddress((void**)&wphi, g_wphi);
    cudaGetSymbolAddress((void**)&wplo, g_wplo);

    const int gru_smem = 24 * 512 * 4 + 16 * 12 * 64 * 4;  // 98304 B
    cudaFuncSetAttribute(gru_kernel, cudaFuncAttributeMaxDynamicSharedMemorySize, gru_smem);
    cudaFuncSetAttribute(mmagemm_kernel, cudaFuncAttributeMaxDynamicSharedMemorySize, MM_SMEM);

    init_kernel<<<64, 256>>>();
    convx_kernel<<<BT_ * F_ / 4 / 256, 256>>>(x);
    convw_kernel<<<(F_ * G_ + 255) / 256, 256>>>(Wf, wfhi, wflo, F_ * G_);
    convw_kernel<<<(F_ * G_ + 255) / 256, 256>>>(Wb, wbhi, wblo, F_ * G_);
    convw_kernel<<<(F_ * P_ + 255) / 256, 256>>>(Wp, wphi, wplo, F_ * P_);

    mmagemm_kernel<<<dim3(BT_ / 128, 48), 256, MM_SMEM>>>(bf, bb, 0);
    mmagemm_kernel<<<dim3(BT_ / 128, 16), 256, MM_SMEM>>>(nullptr, nullptr, 1);

    gru_kernel<<<128, 512, gru_smem>>>(Uf, Ub, bf, bb);
    ln_kernel<<<B_ * T_, 256>>>(gamma, beta, out);
}